// round 6
// baseline (speedup 1.0000x reference)
#include <cuda_runtime.h>

#define HID   512
#define BATCH 256
#define TLEN  1024
#define GRID  128
#define NTHR  512
#define UNITS 4          // hidden units per block per layer (128*4 = 512)
#define HPAD  16         // h array row padding for prefetch over-read

// Persistent device state, [k][b] layout (batch contiguous).
__device__ float g_h1[2][(HID + HPAD) * BATCH];
__device__ float g_h2[2][(HID + HPAD) * BATCH];
__device__ float g_xT[TLEN * BATCH];     // x transposed to [t][b]
__device__ unsigned long long g_epoch;
__device__ unsigned g_cnt;

__device__ __forceinline__ float sigm(float v) {
    return 1.0f / (1.0f + __expf(-v));
}

__device__ __forceinline__ unsigned long long pack2(float lo, float hi) {
    unsigned long long r;
    asm("mov.b64 %0, {%1, %2};" : "=l"(r) : "f"(lo), "f"(hi));
    return r;
}
__device__ __forceinline__ unsigned long long fma2(unsigned long long a,
                                                   unsigned long long b,
                                                   unsigned long long c) {
    unsigned long long d;
    asm("fma.rn.f32x2 %0, %1, %2, %3;" : "=l"(d) : "l"(a), "l"(b), "l"(c));
    return d;
}

// Grid-wide barrier: all GRID blocks co-resident (1 block/SM, 128 <= 148 SMs).
__device__ __forceinline__ void grid_bar(unsigned long long& target) {
    __threadfence();          // release
    __syncthreads();
    if (threadIdx.x == 0) {
        target += 1;
        unsigned prev = atomicAdd(&g_cnt, 1u);
        if (prev == GRID - 1) {
            g_cnt = 0;
            __threadfence();
            atomicAdd(&g_epoch, 1ull);
        } else {
            while (*((volatile unsigned long long*)&g_epoch) < target) { }
        }
        __threadfence();      // acquire
    }
    __syncthreads();
}

// Per-k inner op: w_ = duplicated weight pair for rows (2p, 2p+1),
// h_ = 4 batch values as 2 packed f32x2.
#define QSTEP(ACC, W_, H_)                         \
    do {                                           \
        ACC[0] = fma2((W_).x, (H_).x, ACC[0]);     \
        ACC[1] = fma2((W_).x, (H_).y, ACC[1]);     \
        ACC[2] = fma2((W_).y, (H_).x, ACC[2]);     \
        ACC[3] = fma2((W_).y, (H_).y, ACC[3]);     \
    } while (0)

// Pipelined 512-k GEMV pass: h quad stream prefetched one 8-body ahead,
// ping-pong buffers (no rotation movs). HP = h base, WD = dup-weight smem
// (32 floats per k), P_ = row-pair idx, HPQ = HP + 4*q precomputed.
#define GEMV512_Q(ACC, HPQ, WD, P_)                                        \
    do {                                                                   \
        ulonglong2 ha_[8], hb_[8];                                         \
        _Pragma("unroll")                                                  \
        for (int j_ = 0; j_ < 8; j_++)                                     \
            ha_[j_] = *(const ulonglong2*)((HPQ) + j_ * BATCH);            \
        for (int k0_ = 0; k0_ < HID; k0_ += 16) {                          \
            _Pragma("unroll")                                              \
            for (int j_ = 0; j_ < 8; j_++)                                 \
                hb_[j_] = *(const ulonglong2*)((HPQ) + (k0_+8+j_)*BATCH);  \
            _Pragma("unroll")                                              \
            for (int j_ = 0; j_ < 8; j_++) {                               \
                ulonglong2 w_ = *(const ulonglong2*)                       \
                    ((WD) + (k0_ + j_) * 32 + (P_) * 4);                   \
                QSTEP(ACC, w_, ha_[j_]);                                   \
            }                                                              \
            _Pragma("unroll")                                              \
            for (int j_ = 0; j_ < 8; j_++)                                 \
                ha_[j_] = *(const ulonglong2*)((HPQ) + (k0_+16+j_)*BATCH); \
            _Pragma("unroll")                                              \
            for (int j_ = 0; j_ < 8; j_++) {                               \
                ulonglong2 w_ = *(const ulonglong2*)                       \
                    ((WD) + (k0_ + 8 + j_) * 32 + (P_) * 4);               \
                QSTEP(ACC, w_, hb_[j_]);                                   \
            }                                                              \
        }                                                                  \
    } while (0)

__global__ __launch_bounds__(NTHR, 1)
void lstm_persist(const float* __restrict__ x,
                  const float* __restrict__ W_ih1,
                  const float* __restrict__ W_hh1,
                  const float* __restrict__ b1,
                  const float* __restrict__ W_ih2,
                  const float* __restrict__ W_hh2,
                  const float* __restrict__ b2,
                  const float* __restrict__ W_lin,
                  const float* __restrict__ b_lin,
                  float* __restrict__ out)
{
    extern __shared__ float smem[];
    // smem (floats): weights stored DUPLICATED: per k, 16 rows x (w,w) = 32 floats
    float* W1d   = smem;                  // [512][32]
    float* W2d   = W1d + HID * 32;        // [1024][32] (k<512: W_ih2, else W_hh2)
    float* gates = W2d + 2 * HID * 32;    // [16][256] pre-activation exchange
    float* Wih1d = gates + 16 * BATCH;    // [32] dup
    float* b1d   = Wih1d + 32;            // [32] dup
    float* b2d   = b1d + 32;              // [32] dup
    float* Wlins = b2d + 32;              // [512]
    float* red   = Wlins + HID;           // [16] warp partials (pad 32)

    const int tid = threadIdx.x;
    const int bk  = blockIdx.x;
    const int p   = tid >> 6;             // row-pair 0..7 (rows 2p, 2p+1)
    const int q   = tid & 63;             // batch quad 0..63 (batch 4q..4q+3)
    const int a_u  = tid >> 7;            // activation: unit 0..3
    const int a_bp = tid & 127;           // activation: batch pair
    const int base_u = bk * UNITS;

    unsigned long long bar_target = 0;
    if (tid == 0) bar_target = *((volatile unsigned long long*)&g_epoch);

    // ---- load duplicated weight slices ----
    // local row r = 4*u + gate; global row = gate*HID + (base_u + u)
    for (int idx = tid; idx < HID * 16; idx += NTHR) {
        int k = idx >> 4, r = idx & 15;
        int row = (r & 3) * HID + (base_u + (r >> 2));
        float w = W_hh1[row * HID + k];
        W1d[k * 32 + 2 * r] = w;
        W1d[k * 32 + 2 * r + 1] = w;
    }
    for (int idx = tid; idx < 2 * HID * 16; idx += NTHR) {
        int k = idx >> 4, r = idx & 15;
        int row = (r & 3) * HID + (base_u + (r >> 2));
        float w = (k < HID) ? W_ih2[row * HID + k]
                            : W_hh2[row * HID + (k - HID)];
        W2d[k * 32 + 2 * r] = w;
        W2d[k * 32 + 2 * r + 1] = w;
    }
    if (tid < 16) {
        int r = tid;
        int row = (r & 3) * HID + (base_u + (r >> 2));
        float wv = W_ih1[row];
        Wih1d[2 * r] = wv;  Wih1d[2 * r + 1] = wv;
        float bv = b1[row];
        b1d[2 * r] = bv;    b1d[2 * r + 1] = bv;
        float cv = b2[row];
        b2d[2 * r] = cv;    b2d[2 * r + 1] = cv;
    }
    for (int idx = tid; idx < HID; idx += NTHR) Wlins[idx] = W_lin[idx];
    const float blin = b_lin[0];

    // ---- prologue: zero state (incl. padding), transpose x ----
    {
        const int gsz = GRID * NTHR;
        for (int idx = bk * NTHR + tid; idx < TLEN * BATCH; idx += gsz) {
            int bb = idx >> 10;
            int tt = idx & (TLEN - 1);
            g_xT[tt * BATCH + bb] = x[idx];
        }
        for (int idx = bk * NTHR + tid; idx < (HID + HPAD) * BATCH; idx += gsz) {
            g_h1[0][idx] = 0.0f; g_h1[1][idx] = 0.0f;
            g_h2[0][idx] = 0.0f; g_h2[1][idx] = 0.0f;
        }
    }
    grid_bar(bar_target);

    // persistent cell state: this thread's activation partition (unit a_u, 2 batch)
    float c1x = 0.0f, c1y = 0.0f, c2x = 0.0f, c2y = 0.0f;

    unsigned long long acc[4];

    for (int t = 0; t < TLEN; t++) {
        const int par = t & 1;
        const float* __restrict__ h1p = g_h1[par];
        float*       __restrict__ h1n = g_h1[par ^ 1];
        const float* __restrict__ h2p = g_h2[par];
        float*       __restrict__ h2n = g_h2[par ^ 1];

        // ---------- phase A: layer-1 gates ----------
        {
            ulonglong2 wih = *(const ulonglong2*)(Wih1d + p * 4);
            ulonglong2 bb1 = *(const ulonglong2*)(b1d + p * 4);
            ulonglong2 xq  = *(const ulonglong2*)(g_xT + t * BATCH + 4 * q);
            acc[0] = fma2(wih.x, xq.x, bb1.x);
            acc[1] = fma2(wih.x, xq.y, bb1.x);
            acc[2] = fma2(wih.y, xq.x, bb1.y);
            acc[3] = fma2(wih.y, xq.y, bb1.y);

            const float* hpq = h1p + 4 * q;
            GEMV512_Q(acc, hpq, W1d, p);

            // exchange pre-activations via smem
            *(ulonglong2*)(gates + (2 * p)     * BATCH + 4 * q) =
                make_ulonglong2(acc[0], acc[1]);
            *(ulonglong2*)(gates + (2 * p + 1) * BATCH + 4 * q) =
                make_ulonglong2(acc[2], acc[3]);
        }
        __syncthreads();
        // ---------- layer-1 activation (partition: unit a_u, batch pair) ----
        {
            float2 vi = *(const float2*)(gates + (4 * a_u + 0) * BATCH + 2 * a_bp);
            float2 vf = *(const float2*)(gates + (4 * a_u + 1) * BATCH + 2 * a_bp);
            float2 vg = *(const float2*)(gates + (4 * a_u + 2) * BATCH + 2 * a_bp);
            float2 vo = *(const float2*)(gates + (4 * a_u + 3) * BATCH + 2 * a_bp);
            float cx = sigm(vf.x) * c1x + sigm(vi.x) * tanhf(vg.x);
            float cy = sigm(vf.y) * c1y + sigm(vi.y) * tanhf(vg.y);
            c1x = cx; c1y = cy;
            float h0 = sigm(vo.x) * tanhf(cx);
            float h1v = sigm(vo.y) * tanhf(cy);
            *(unsigned long long*)(h1n + (base_u + a_u) * BATCH + 2 * a_bp) =
                pack2(h0, h1v);
        }

        grid_bar(bar_target);   // the only grid barrier per step

        // ---------- output for step t-1 (h2 from phase B(t-1)) ----------
        if (t > 0) {
            const int half = tid >> 8;
            const int j = tid & 255;
            const int bb = bk * 2 + half;
            float s = Wlins[j]       * h2p[j * BATCH + bb]
                    + Wlins[j + 256] * h2p[(j + 256) * BATCH + bb];
#pragma unroll
            for (int o = 16; o > 0; o >>= 1)
                s += __shfl_xor_sync(0xffffffffu, s, o);
            if ((tid & 31) == 0) red[tid >> 5] = s;   // 16 warp partials
            __syncthreads();
            if (j == 0) {
                float r = 0.0f;
#pragma unroll
                for (int w = 0; w < 8; w++) r += red[half * 8 + w];
                out[bb * TLEN + (t - 1)] = r + blin;
            }
        }

        // ---------- phase B: layer-2 gates ----------
        {
            ulonglong2 bb2 = *(const ulonglong2*)(b2d + p * 4);
            acc[0] = bb2.x; acc[1] = bb2.x;
            acc[2] = bb2.y; acc[3] = bb2.y;

            const float* hq1 = h1n + 4 * q;
            GEMV512_Q(acc, hq1, W2d, p);                 // input = h1 (new)
            const float* hq2 = h2p + 4 * q;
            GEMV512_Q(acc, hq2, W2d + HID * 32, p);      // recurrent = h2 (prev)

            __syncthreads();   // gates buffer free (phase-A readers done via bar)
            *(ulonglong2*)(gates + (2 * p)     * BATCH + 4 * q) =
                make_ulonglong2(acc[0], acc[1]);
            *(ulonglong2*)(gates + (2 * p + 1) * BATCH + 4 * q) =
                make_ulonglong2(acc[2], acc[3]);
        }
        __syncthreads();
        // ---------- layer-2 activation ----------
        {
            float2 vi = *(const float2*)(gates + (4 * a_u + 0) * BATCH + 2 * a_bp);
            float2 vf = *(const float2*)(gates + (4 * a_u + 1) * BATCH + 2 * a_bp);
            float2 vg = *(const float2*)(gates + (4 * a_u + 2) * BATCH + 2 * a_bp);
            float2 vo = *(const float2*)(gates + (4 * a_u + 3) * BATCH + 2 * a_bp);
            float cx = sigm(vf.x) * c2x + sigm(vi.x) * tanhf(vg.x);
            float cy = sigm(vf.y) * c2y + sigm(vi.y) * tanhf(vg.y);
            c2x = cx; c2y = cy;
            float h0 = sigm(vo.x) * tanhf(cx);
            float h1v = sigm(vo.y) * tanhf(cy);
            *(unsigned long long*)(h2n + (base_u + a_u) * BATCH + 2 * a_bp) =
                pack2(h0, h1v);
        }
    }

    // ---------- final output (t = TLEN-1) ----------
    grid_bar(bar_target);
    {
        const float* __restrict__ h2f = g_h2[0];   // TLEN even: last write buf 0
        const int half = tid >> 8;
        const int j = tid & 255;
        const int bb = bk * 2 + half;
        float s = Wlins[j]       * h2f[j * BATCH + bb]
                + Wlins[j + 256] * h2f[(j + 256) * BATCH + bb];
#pragma unroll
        for (int o = 16; o > 0; o >>= 1)
            s += __shfl_xor_sync(0xffffffffu, s, o);
        if ((tid & 31) == 0) red[tid >> 5] = s;
        __syncthreads();
        if (j == 0) {
            float r = 0.0f;
#pragma unroll
            for (int w = 0; w < 8; w++) r += red[half * 8 + w];
            out[bb * TLEN + (TLEN - 1)] = r + blin;
        }
    }
}

extern "C" void kernel_launch(void* const* d_in, const int* in_sizes, int n_in,
                              void* d_out, int out_size)
{
    (void)in_sizes; (void)n_in; (void)out_size;
    const float* x     = (const float*)d_in[0];
    const float* W_ih1 = (const float*)d_in[1];
    const float* W_hh1 = (const float*)d_in[2];
    const float* b1    = (const float*)d_in[3];
    const float* W_ih2 = (const float*)d_in[4];
    const float* W_hh2 = (const float*)d_in[5];
    const float* b2    = (const float*)d_in[6];
    const float* W_lin = (const float*)d_in[7];
    const float* b_lin = (const float*)d_in[8];
    float* out = (float*)d_out;

    const size_t smem_bytes =
        (size_t)(HID * 32 + 2 * HID * 32 + 16 * BATCH
                 + 32 + 32 + 32 + HID + 32) * sizeof(float);

    cudaFuncSetAttribute(lstm_persist,
                         cudaFuncAttributeMaxDynamicSharedMemorySize,
                         (int)smem_bytes);

    lstm_persist<<<GRID, NTHR, smem_bytes>>>(
        x, W_ih1, W_hh1, b1, W_ih2, W_hh2, b2, W_lin, b_lin, out);
}

// round 7
// speedup vs baseline: 1.2699x; 1.2699x over previous
#include <cuda_runtime.h>

#define HID   512
#define BATCH 256
#define TLEN  1024
#define GRID  128
#define NTHR  512
#define UNITS 4          // hidden units per block per layer (128*4 = 512)
#define PF    8          // prefetch depth

// Persistent device state (padded so the prefetch pipeline can over-read).
__device__ float g_h1[2][HID * BATCH + PF * BATCH];   // [k][b] transposed
__device__ float g_h2[2][HID * BATCH + PF * BATCH];
__device__ float g_xT[TLEN * BATCH];                  // x transposed to [t][b]
__device__ unsigned long long g_epoch;
__device__ unsigned g_cnt;

__device__ __forceinline__ float sigm(float v) {
    return 1.0f / (1.0f + __expf(-v));
}

__device__ __forceinline__ unsigned long long pack2(float lo, float hi) {
    unsigned long long r;
    asm("mov.b64 %0, {%1, %2};" : "=l"(r) : "f"(lo), "f"(hi));
    return r;
}
__device__ __forceinline__ void unpack2(unsigned long long v, float& lo, float& hi) {
    asm("mov.b64 {%0, %1}, %2;" : "=f"(lo), "=f"(hi) : "l"(v));
}
__device__ __forceinline__ unsigned long long fma2(unsigned long long a,
                                                   unsigned long long b,
                                                   unsigned long long c) {
    unsigned long long d;
    asm("fma.rn.f32x2 %0, %1, %2, %3;" : "=l"(d) : "l"(a), "l"(b), "l"(c));
    return d;
}

// Grid-wide barrier: all GRID blocks co-resident (1 block/SM, 128 <= 148 SMs).
__device__ __forceinline__ void grid_bar(unsigned long long& target) {
    __threadfence();          // release
    __syncthreads();
    if (threadIdx.x == 0) {
        target += 1;
        unsigned prev = atomicAdd(&g_cnt, 1u);
        if (prev == GRID - 1) {
            g_cnt = 0;
            __threadfence();
            atomicAdd(&g_epoch, 1ull);
        } else {
            while (*((volatile unsigned long long*)&g_epoch) < target) { }
        }
        __threadfence();      // acquire
    }
    __syncthreads();
}

// 4 packed FMAs: this thread-half's 8 rows (4 row-pairs) for one k.
#define FMA2x4(ACC, HV2, WB)                                         \
    do {                                                             \
        ulonglong2 q0_ = (WB)[0], q1_ = (WB)[1];                     \
        ACC[0] = fma2(q0_.x, (HV2), ACC[0]);                         \
        ACC[1] = fma2(q0_.y, (HV2), ACC[1]);                         \
        ACC[2] = fma2(q1_.x, (HV2), ACC[2]);                         \
        ACC[3] = fma2(q1_.y, (HV2), ACC[3]);                         \
    } while (0)

// Pipelined 512-k GEMV pass, h stream prefetched one PF-body ahead.
// HP = h base (+b applied by caller), WSH = weight smem base already offset
// by this half's 8 rows (16 floats per k stride).
#define GEMV512_PIPE(ACC, HP, WSH, B_)                                \
    do {                                                              \
        float hbuf_[PF];                                              \
        _Pragma("unroll")                                             \
        for (int j_ = 0; j_ < PF; j_++)                               \
            hbuf_[j_] = (HP)[j_ * BATCH + (B_)];                      \
        for (int k0_ = 0; k0_ < HID; k0_ += PF) {                     \
            float hnext_[PF];                                         \
            _Pragma("unroll")                                         \
            for (int j_ = 0; j_ < PF; j_++)                           \
                hnext_[j_] = (HP)[(k0_ + PF + j_) * BATCH + (B_)];    \
            _Pragma("unroll")                                         \
            for (int j_ = 0; j_ < PF; j_++) {                         \
                unsigned long long hv2_ = pack2(hbuf_[j_], hbuf_[j_]);\
                const ulonglong2* wb_ =                               \
                    (const ulonglong2*)((WSH) + ((k0_ + j_) << 4));   \
                FMA2x4(ACC, hv2_, wb_);                               \
            }                                                         \
            _Pragma("unroll")                                         \
            for (int j_ = 0; j_ < PF; j_++) hbuf_[j_] = hnext_[j_];   \
        }                                                             \
    } while (0)

__global__ __launch_bounds__(NTHR, 1)
void lstm_persist(const float* __restrict__ x,
                  const float* __restrict__ W_ih1,
                  const float* __restrict__ W_hh1,
                  const float* __restrict__ b1,
                  const float* __restrict__ W_ih2,
                  const float* __restrict__ W_hh2,
                  const float* __restrict__ b2,
                  const float* __restrict__ W_lin,
                  const float* __restrict__ b_lin,
                  float* __restrict__ out)
{
    extern __shared__ float smem[];
    // smem layout (floats), 16B aligned (same as R5):
    float* W1s   = smem;                 // [512][16]  k-major, slot r = 4*u+gate
    float* W2s   = W1s + HID * 16;       // [1024][16] (k<512: W_ih2, k>=512: W_hh2)
    float* Wih1s = W2s + 2 * HID * 16;   // [16]
    float* b1s   = Wih1s + 16;           // [16]
    float* b2s   = b1s + 16;             // [16]
    float* Wlins = b2s + 16;             // [512]
    float* red   = Wlins + HID;          // [16] warp partials (pad 32)

    const int tid  = threadIdx.x;
    const int bk   = blockIdx.x;
    const int half = tid >> 8;           // 0: rows 0-7 (units 0-1), 1: rows 8-15
    const int b    = tid & 255;          // batch column
    const int base_u = bk * UNITS;

    unsigned long long bar_target = 0;
    if (tid == 0) bar_target = *((volatile unsigned long long*)&g_epoch);

    // ---- load this block's weight slice into shared memory ----
    // local row r = 4*u + gate; global row = gate*HID + (base_u + u)
    for (int idx = tid; idx < HID * 16; idx += NTHR) {
        int k = idx >> 4, r = idx & 15;
        int row = (r & 3) * HID + (base_u + (r >> 2));
        W1s[idx] = W_hh1[row * HID + k];
    }
    for (int idx = tid; idx < 2 * HID * 16; idx += NTHR) {
        int k = idx >> 4, r = idx & 15;
        int row = (r & 3) * HID + (base_u + (r >> 2));
        W2s[idx] = (k < HID) ? W_ih2[row * HID + k]
                             : W_hh2[row * HID + (k - HID)];
    }
    if (tid < 16) {
        int r = tid;
        int row = (r & 3) * HID + (base_u + (r >> 2));
        Wih1s[r] = W_ih1[row];
        b1s[r]   = b1[row];
        b2s[r]   = b2[row];
    }
    for (int idx = tid; idx < HID; idx += NTHR) Wlins[idx] = W_lin[idx];
    const float blin = b_lin[0];

    // ---- prologue: zero initial state (incl. padding), transpose x ----
    {
        const int gsz = GRID * NTHR;
        for (int idx = bk * NTHR + tid; idx < TLEN * BATCH; idx += gsz) {
            int bb = idx >> 10;          // /TLEN
            int tt = idx & (TLEN - 1);
            g_xT[tt * BATCH + bb] = x[idx];
        }
        for (int idx = bk * NTHR + tid; idx < (HID + PF) * BATCH; idx += gsz) {
            g_h1[0][idx] = 0.0f; g_h1[1][idx] = 0.0f;
            g_h2[0][idx] = 0.0f; g_h2[1][idx] = 0.0f;
        }
    }
    grid_bar(bar_target);

    // this thread owns units (2*half, 2*half+1) for batch b
    float c1[2] = {0.0f, 0.0f};
    float c2[2] = {0.0f, 0.0f};

    // 4 packed accumulators: acc[2u+0]=(i,f), acc[2u+1]=(g,o) of local unit u
    unsigned long long acc[4];

    const unsigned long long* Wih1p =
        (const unsigned long long*)Wih1s + 4 * half;
    const unsigned long long* b1p =
        (const unsigned long long*)b1s + 4 * half;
    const unsigned long long* b2p =
        (const unsigned long long*)b2s + 4 * half;
    float* W1h = W1s + 8 * half;
    float* W2h = W2s + 8 * half;

    for (int t = 0; t < TLEN; t++) {
        const int par = t & 1;
        const float* __restrict__ h1p = g_h1[par];
        float*       __restrict__ h1n = g_h1[par ^ 1];
        const float* __restrict__ h2p = g_h2[par];
        float*       __restrict__ h2n = g_h2[par ^ 1];

        // ---------- phase A: layer-1 gates + cell update ----------
        {
            const float xv = g_xT[t * BATCH + b];
            const unsigned long long xv2 = pack2(xv, xv);
#pragma unroll
            for (int j = 0; j < 4; j++) acc[j] = fma2(Wih1p[j], xv2, b1p[j]);

            GEMV512_PIPE(acc, h1p, W1h, b);

#pragma unroll
            for (int u = 0; u < 2; u++) {
                float pi, pf, pg, po;
                unpack2(acc[2 * u + 0], pi, pf);
                unpack2(acc[2 * u + 1], pg, po);
                float c = sigm(pf) * c1[u] + sigm(pi) * tanhf(pg);
                c1[u] = c;
                h1n[(base_u + 2 * half + u) * BATCH + b] = sigm(po) * tanhf(c);
            }
        }

        grid_bar(bar_target);   // the only grid barrier per step

        // ---------- output for step t-1 (reads h2 produced by phase B(t-1)) ----
        if (t > 0) {
            const int bb = bk * 2 + half;
            float s = Wlins[b]       * h2p[b * BATCH + bb]
                    + Wlins[b + 256] * h2p[(b + 256) * BATCH + bb];
#pragma unroll
            for (int o = 16; o > 0; o >>= 1)
                s += __shfl_xor_sync(0xffffffffu, s, o);
            if ((tid & 31) == 0) red[tid >> 5] = s;   // 16 warp partials
            __syncthreads();
            if (b == 0) {
                float r = 0.0f;
#pragma unroll
                for (int w = 0; w < 8; w++) r += red[half * 8 + w];
                out[bb * TLEN + (t - 1)] = r + blin;
            }
        }

        // ---------- phase B: layer-2 gates + cell update ----------
        {
#pragma unroll
            for (int j = 0; j < 4; j++) acc[j] = b2p[j];

            GEMV512_PIPE(acc, h1n, W2h, b);                // input = h1 (new)
            GEMV512_PIPE(acc, h2p, (W2h + HID * 16), b);   // recurrent = h2 (prev)

#pragma unroll
            for (int u = 0; u < 2; u++) {
                float pi, pf, pg, po;
                unpack2(acc[2 * u + 0], pi, pf);
                unpack2(acc[2 * u + 1], pg, po);
                float c = sigm(pf) * c2[u] + sigm(pi) * tanhf(pg);
                c2[u] = c;
                h2n[(base_u + 2 * half + u) * BATCH + b] = sigm(po) * tanhf(c);
            }
        }
    }

    // ---------- final output (t = TLEN-1) ----------
    grid_bar(bar_target);
    {
        const float* __restrict__ h2f = g_h2[0];   // TLEN even: last write buf 0
        const int bb = bk * 2 + half;
        float s = Wlins[b]       * h2f[b * BATCH + bb]
                + Wlins[b + 256] * h2f[(b + 256) * BATCH + bb];
#pragma unroll
        for (int o = 16; o > 0; o >>= 1)
            s += __shfl_xor_sync(0xffffffffu, s, o);
        if ((tid & 31) == 0) red[tid >> 5] = s;
        __syncthreads();
        if (b == 0) {
            float r = 0.0f;
#pragma unroll
            for (int w = 0; w < 8; w++) r += red[half * 8 + w];
            out[bb * TLEN + (TLEN - 1)] = r + blin;
        }
    }
}

extern "C" void kernel_launch(void* const* d_in, const int* in_sizes, int n_in,
                              void* d_out, int out_size)
{
    (void)in_sizes; (void)n_in; (void)out_size;
    const float* x     = (const float*)d_in[0];
    const float* W_ih1 = (const float*)d_in[1];
    const float* W_hh1 = (const float*)d_in[2];
    const float* b1    = (const float*)d_in[3];
    const float* W_ih2 = (const float*)d_in[4];
    const float* W_hh2 = (const float*)d_in[5];
    const float* b2    = (const float*)d_in[6];
    const float* W_lin = (const float*)d_in[7];
    const float* b_lin = (const float*)d_in[8];
    float* out = (float*)d_out;

    const size_t smem_bytes =
        (size_t)(HID * 16 + 2 * HID * 16 + 16 + 16 + 16 + HID + 32) * sizeof(float);

    cudaFuncSetAttribute(lstm_persist,
                         cudaFuncAttributeMaxDynamicSharedMemorySize,
                         (int)smem_bytes);

    lstm_persist<<<GRID, NTHR, smem_bytes>>>(
        x, W_ih1, W_hh1, b1, W_ih2, W_hh2, b2, W_lin, b_lin, out);
}